// round 6
// baseline (speedup 1.0000x reference)
#include <cuda_runtime.h>
#include <math.h>

#define IMG   112
#define CCH   192
#define NPIX  (32*IMG*IMG)         // 401408 pixels
#define TW    28
#define TH    4
#define HALO  3
#define HDW   (TW + 2*HALO)        // 34
#define HDH   (TH + 2*HALO)        // 10
#define NHP   (HDW*HDH)            // 340
#define NT    256
#define NW    (NT/32)              // 8
#define F4    (CCH/4)              // 48
#define RBLOCKS (148*8)            // 1184 reduce blocks

// pooled[pix*2+0]=avg, [pix*2+1]=max  (3.2 MB, L2-resident)
__device__ float g_pooled[NPIX * 2];

// ---------------- Kernel A: channel avg/max reduction (grid-stride) ----------------
__global__ __launch_bounds__(NT, 8)
void reduce_kernel(const float* __restrict__ x)
{
    const int lane   = threadIdx.x & 31;
    const int gwarp  = blockIdx.x * NW + (threadIdx.x >> 5);
    const int nwarps = RBLOCKS * NW;     // 9472

    #pragma unroll 2
    for (int pix = gwarp; pix < NPIX; pix += nwarps) {
        const float4* px4 = reinterpret_cast<const float4*>(x + (size_t)pix * CCH);
        float4 a = __ldcs(px4 + lane);
        float s = (a.x + a.y) + (a.z + a.w);
        float m = fmaxf(fmaxf(a.x, a.y), fmaxf(a.z, a.w));
        if (lane < 16) {
            float4 bq = __ldcs(px4 + 32 + lane);
            s += (bq.x + bq.y) + (bq.z + bq.w);
            m  = fmaxf(m, fmaxf(fmaxf(bq.x, bq.y), fmaxf(bq.z, bq.w)));
        }
        #pragma unroll
        for (int o = 16; o > 0; o >>= 1) {
            s += __shfl_xor_sync(0xffffffffu, s, o);
            m  = fmaxf(m, __shfl_xor_sync(0xffffffffu, m, o));
        }
        if (lane == 0) {
            float2 r = make_float2(s * (1.0f / CCH), m);
            *reinterpret_cast<float2*>(&g_pooled[(size_t)pix * 2]) = r;
        }
    }
}

// ---------------- Kernel B: conv + sigmoid + apply ----------------
__global__ __launch_bounds__(NT, 8)
void apply_kernel(const float* __restrict__ x,
                  const float* __restrict__ w,
                  float* __restrict__ out)
{
    __shared__ float s_avg[NHP];
    __shared__ float s_max[NHP];
    __shared__ float s_att[TW*TH];
    __shared__ float s_w[98];

    const int tid = threadIdx.x;
    if (tid < 98) s_w[tid] = w[tid];

    const int TPX = IMG / TW;                // 4
    const int TPY = IMG / TH;                // 28
    int bidx = blockIdx.x;
    int b    = bidx / (TPX*TPY);
    int tr   = bidx % (TPX*TPY);
    int ty0  = (tr / TPX) * TH;
    int tx0  = (tr % TPX) * TW;

    // ---- Phase 1: load pooled halo (tiny, L2-hot) ----
    for (int p = tid; p < NHP; p += NT) {
        int hy = ty0 + p / HDW - HALO;
        int wx = tx0 + p % HDW - HALO;
        float a = 0.f, m = 0.f;
        if (hy >= 0 && hy < IMG && wx >= 0 && wx < IMG) {
            size_t pix = ((size_t)b * IMG + hy) * IMG + wx;
            float2 r = *reinterpret_cast<const float2*>(&g_pooled[pix * 2]);
            a = r.x; m = r.y;
        }
        s_avg[p] = a;
        s_max[p] = m;
    }
    __syncthreads();

    // ---- Phase 2: 7x7 conv (cross-correlation) + sigmoid ----
    if (tid < TW*TH) {
        int oy = tid / TW, ox = tid % TW;
        float acc = 0.f;
        #pragma unroll
        for (int kh = 0; kh < 7; kh++) {
            #pragma unroll
            for (int kw = 0; kw < 7; kw++) {
                int p = (oy + kh) * HDW + (ox + kw);
                acc = fmaf(s_avg[p], s_w[(kh*7 + kw)*2 + 0], acc);
                acc = fmaf(s_max[p], s_w[(kh*7 + kw)*2 + 1], acc);
            }
        }
        s_att[tid] = 1.0f / (1.0f + __expf(-acc));
    }
    __syncthreads();

    // ---- Phase 3: out = x * att, float4 streaming, unroll-3 ----
    // total4 = 28*4*48 = 5376 = 7 * (NT*3)  -> no remainder, no guards
    const int total4 = TW*TH*F4;
    #pragma unroll 1
    for (int k = tid; k < total4; k += NT*3) {
        float4 v[3]; float a[3]; size_t g[3];
        #pragma unroll
        for (int u = 0; u < 3; u++) {
            int kk = k + u*NT;
            int pt = kk / F4;
            int c4 = kk - pt * F4;
            int oy = pt / TW, ox = pt - oy * TW;
            g[u] = (((size_t)b * IMG + (ty0 + oy)) * IMG + (tx0 + ox)) * CCH + (size_t)c4 * 4;
            v[u] = __ldcs(reinterpret_cast<const float4*>(x + g[u]));
            a[u] = s_att[pt];
        }
        #pragma unroll
        for (int u = 0; u < 3; u++) {
            float4 r = v[u]; float s = a[u];
            r.x *= s; r.y *= s; r.z *= s; r.w *= s;
            __stcs(reinterpret_cast<float4*>(out + g[u]), r);
        }
    }
}

extern "C" void kernel_launch(void* const* d_in, const int* in_sizes, int n_in,
                              void* d_out, int out_size)
{
    const float* x = (const float*)d_in[0];
    const float* w = (const float*)d_in[1];
    float* out = (float*)d_out;

    reduce_kernel<<<RBLOCKS, NT>>>(x);

    const int TPX = IMG / TW, TPY = IMG / TH;   // 4, 28
    apply_kernel<<<32 * TPX * TPY, NT>>>(x, w, out);   // 3584 blocks
}

// round 7
// speedup vs baseline: 1.0292x; 1.0292x over previous
#include <cuda_runtime.h>
#include <math.h>

#define IMG   112
#define CCH   192
#define NPIX  (32*IMG*IMG)         // 401408 pixels
#define NPAIR (NPIX/2)             // 200704
#define TW    28
#define TH    8
#define HALO  3
#define HDW   (TW + 2*HALO)        // 34
#define HDH   (TH + 2*HALO)        // 14
#define NHP   (HDW*HDH)            // 476
#define NT    256
#define NW    (NT/32)              // 8
#define F4    (CCH/4)              // 48

// pooled[pix*2+0]=avg, [pix*2+1]=max  (3.2 MB, L2-resident)
__device__ float g_pooled[NPIX * 2];
// attention map (1.6 MB, L2-resident)
__device__ float g_att[NPIX];

__device__ __forceinline__ float hsum(float4 v) { return (v.x + v.y) + (v.z + v.w); }
__device__ __forceinline__ float hmax(float4 v) { return fmaxf(fmaxf(v.x, v.y), fmaxf(v.z, v.w)); }

// ---------------- Kernel A: channel avg/max, 2 pixels per warp ----------------
__global__ __launch_bounds__(NT, 8)
void reduce_kernel(const float* __restrict__ x)
{
    const int lane = threadIdx.x & 31;
    const int pair = blockIdx.x * NW + (threadIdx.x >> 5);   // < NPAIR exactly

    const float4* p = reinterpret_cast<const float4*>(x + (size_t)pair * 2 * CCH);
    float4 a0 = __ldcs(p + lane);          // f4 [0,32)   -> pixel 0
    float4 a1 = __ldcs(p + 32 + lane);     // f4 [32,64)  -> px0 (lane<16) / px1 (lane>=16)
    float4 a2 = __ldcs(p + 64 + lane);     // f4 [64,96)  -> pixel 1

    float s0 = hsum(a0), m0 = hmax(a0);
    float s1 = hsum(a2), m1 = hmax(a2);
    float sm = hsum(a1), mm = hmax(a1);
    if (lane < 16) { s0 += sm; m0 = fmaxf(m0, mm); }
    else           { s1 += sm; m1 = fmaxf(m1, mm); }

    #pragma unroll
    for (int o = 16; o > 0; o >>= 1) {
        s0 += __shfl_xor_sync(0xffffffffu, s0, o);
        s1 += __shfl_xor_sync(0xffffffffu, s1, o);
        m0  = fmaxf(m0, __shfl_xor_sync(0xffffffffu, m0, o));
        m1  = fmaxf(m1, __shfl_xor_sync(0xffffffffu, m1, o));
    }
    if (lane == 0) {
        float4 r = make_float4(s0 * (1.0f / CCH), m0, s1 * (1.0f / CCH), m1);
        *reinterpret_cast<float4*>(&g_pooled[(size_t)pair * 4]) = r;
    }
}

// ---------------- Kernel B: 7x7 conv + sigmoid -> g_att ----------------
__global__ __launch_bounds__(NT, 8)
void conv_kernel(const float* __restrict__ w)
{
    __shared__ float s_avg[NHP];
    __shared__ float s_max[NHP];
    __shared__ float s_w[98];

    const int tid = threadIdx.x;
    if (tid < 98) s_w[tid] = w[tid];

    const int TPX = IMG / TW;                // 4
    const int TPY = IMG / TH;                // 14
    int bidx = blockIdx.x;
    int b    = bidx / (TPX*TPY);
    int tr   = bidx % (TPX*TPY);
    int ty0  = (tr / TPX) * TH;
    int tx0  = (tr % TPX) * TW;

    for (int p = tid; p < NHP; p += NT) {
        int hy = ty0 + p / HDW - HALO;
        int wx = tx0 + p % HDW - HALO;
        float a = 0.f, m = 0.f;
        if (hy >= 0 && hy < IMG && wx >= 0 && wx < IMG) {
            size_t pix = ((size_t)b * IMG + hy) * IMG + wx;
            float2 r = *reinterpret_cast<const float2*>(&g_pooled[pix * 2]);
            a = r.x; m = r.y;
        }
        s_avg[p] = a;
        s_max[p] = m;
    }
    __syncthreads();

    if (tid < TW*TH) {
        int oy = tid / TW, ox = tid % TW;
        float acc = 0.f;
        #pragma unroll
        for (int kh = 0; kh < 7; kh++) {
            #pragma unroll
            for (int kw = 0; kw < 7; kw++) {
                int p = (oy + kh) * HDW + (ox + kw);
                acc = fmaf(s_avg[p], s_w[(kh*7 + kw)*2 + 0], acc);
                acc = fmaf(s_max[p], s_w[(kh*7 + kw)*2 + 1], acc);
            }
        }
        size_t pix = ((size_t)b * IMG + (ty0 + oy)) * IMG + (tx0 + ox);
        g_att[pix] = 1.0f / (1.0f + __expf(-acc));
    }
}

// ---------------- Kernel C: out = x * att, pure stream ----------------
// total float4 = NPIX*48 = 19,267,584 = 18816 * 1024 exactly
__global__ __launch_bounds__(NT, 8)
void apply_kernel(const float* __restrict__ x,
                  float* __restrict__ out)
{
    size_t base = (size_t)blockIdx.x * (NT*4) + threadIdx.x;
    float4 v[4]; float a[4];
    #pragma unroll
    for (int u = 0; u < 4; u++) {
        size_t k = base + (size_t)u * NT;
        v[u] = __ldcs(reinterpret_cast<const float4*>(x) + k);
        a[u] = __ldg(&g_att[k / F4]);
    }
    #pragma unroll
    for (int u = 0; u < 4; u++) {
        size_t k = base + (size_t)u * NT;
        float4 r = v[u]; float s = a[u];
        r.x *= s; r.y *= s; r.z *= s; r.w *= s;
        __stcs(reinterpret_cast<float4*>(out) + k, r);
    }
}

extern "C" void kernel_launch(void* const* d_in, const int* in_sizes, int n_in,
                              void* d_out, int out_size)
{
    const float* x = (const float*)d_in[0];
    const float* w = (const float*)d_in[1];
    float* out = (float*)d_out;

    reduce_kernel<<<NPAIR / NW, NT>>>(x);                 // 25088 blocks

    const int TPX = IMG / TW, TPY = IMG / TH;             // 4, 14
    conv_kernel<<<32 * TPX * TPY, NT>>>(w);               // 1792 blocks

    apply_kernel<<<NPIX * F4 / (NT*4), NT>>>(x, out);     // 18816 blocks
}

// round 8
// speedup vs baseline: 1.0570x; 1.0270x over previous
#include <cuda_runtime.h>
#include <math.h>

#define IMG   112
#define CCH   192
#define NPIX  (32*IMG*IMG)         // 401408 pixels
#define NPAIR (NPIX/2)             // 200704
#define TW    28
#define TH    8
#define HALO  3
#define HDW   (TW + 2*HALO)        // 34
#define HDH   (TH + 2*HALO)        // 14
#define NHP   (HDW*HDH)            // 476
#define NT    256
#define NW    (NT/32)              // 8
#define F4    (CCH/4)              // 48

// pooled[pix*2+0]=avg, [pix*2+1]=max  (3.2 MB, L2-resident)
__device__ float g_pooled[NPIX * 2];

__device__ __forceinline__ float hsum(float4 v) { return (v.x + v.y) + (v.z + v.w); }
__device__ __forceinline__ float hmax(float4 v) { return fmaxf(fmaxf(v.x, v.y), fmaxf(v.z, v.w)); }

// ---------------- Kernel A: channel avg/max, 2 pixels per warp ----------------
__global__ __launch_bounds__(NT, 8)
void reduce_kernel(const float* __restrict__ x)
{
    const int lane = threadIdx.x & 31;
    const int pair = blockIdx.x * NW + (threadIdx.x >> 5);   // < NPAIR exactly

    const float4* p = reinterpret_cast<const float4*>(x + (size_t)pair * 2 * CCH);
    float4 a0 = __ldcs(p + lane);          // f4 [0,32)   -> pixel 0
    float4 a1 = __ldcs(p + 32 + lane);     // f4 [32,64)  -> px0 (lane<16) / px1 (lane>=16)
    float4 a2 = __ldcs(p + 64 + lane);     // f4 [64,96)  -> pixel 1

    float s0 = hsum(a0), m0 = hmax(a0);
    float s1 = hsum(a2), m1 = hmax(a2);
    float sm = hsum(a1), mm = hmax(a1);
    if (lane < 16) { s0 += sm; m0 = fmaxf(m0, mm); }
    else           { s1 += sm; m1 = fmaxf(m1, mm); }

    #pragma unroll
    for (int o = 16; o > 0; o >>= 1) {
        s0 += __shfl_xor_sync(0xffffffffu, s0, o);
        s1 += __shfl_xor_sync(0xffffffffu, s1, o);
        m0  = fmaxf(m0, __shfl_xor_sync(0xffffffffu, m0, o));
        m1  = fmaxf(m1, __shfl_xor_sync(0xffffffffu, m1, o));
    }
    if (lane == 0) {
        float4 r = make_float4(s0 * (1.0f / CCH), m0, s1 * (1.0f / CCH), m1);
        *reinterpret_cast<float4*>(&g_pooled[(size_t)pair * 4]) = r;
    }
}

// ---------------- Kernel B: conv + sigmoid + apply (fused, R5 shape) ----------------
__global__ __launch_bounds__(NT, 8)
void apply_kernel(const float* __restrict__ x,
                  const float* __restrict__ w,
                  float* __restrict__ out)
{
    __shared__ float s_avg[NHP];
    __shared__ float s_max[NHP];
    __shared__ float s_att[TW*TH];
    __shared__ float s_w[98];

    const int tid = threadIdx.x;
    if (tid < 98) s_w[tid] = w[tid];

    const int TPX = IMG / TW;                // 4
    const int TPY = IMG / TH;                // 14
    int bidx = blockIdx.x;
    int b    = bidx / (TPX*TPY);
    int tr   = bidx % (TPX*TPY);
    int ty0  = (tr / TPX) * TH;
    int tx0  = (tr % TPX) * TW;

    // ---- Phase 1: load pooled halo (tiny, L2-hot) ----
    for (int p = tid; p < NHP; p += NT) {
        int hy = ty0 + p / HDW - HALO;
        int wx = tx0 + p % HDW - HALO;
        float a = 0.f, m = 0.f;
        if (hy >= 0 && hy < IMG && wx >= 0 && wx < IMG) {
            size_t pix = ((size_t)b * IMG + hy) * IMG + wx;
            float2 r = *reinterpret_cast<const float2*>(&g_pooled[pix * 2]);
            a = r.x; m = r.y;
        }
        s_avg[p] = a;
        s_max[p] = m;
    }
    __syncthreads();

    // ---- Phase 2: 7x7 conv (cross-correlation) + sigmoid ----
    if (tid < TW*TH) {
        int oy = tid / TW, ox = tid % TW;
        float acc = 0.f;
        #pragma unroll
        for (int kh = 0; kh < 7; kh++) {
            #pragma unroll
            for (int kw = 0; kw < 7; kw++) {
                int p = (oy + kh) * HDW + (ox + kw);
                acc = fmaf(s_avg[p], s_w[(kh*7 + kw)*2 + 0], acc);
                acc = fmaf(s_max[p], s_w[(kh*7 + kw)*2 + 1], acc);
            }
        }
        s_att[tid] = 1.0f / (1.0f + __expf(-acc));
    }
    __syncthreads();

    // ---- Phase 3: out = x * att, float4 streaming, unroll-2 ----
    // total4 = 28*8*48 = 10752 = 21 * (NT*2) -> no remainder
    const int total4 = TW*TH*F4;
    #pragma unroll 1
    for (int k = tid; k < total4; k += NT*2) {
        float4 v[2]; float a[2]; size_t g[2];
        #pragma unroll
        for (int u = 0; u < 2; u++) {
            int kk = k + u*NT;
            int pt = kk / F4;
            int c4 = kk - pt * F4;
            int oy = pt / TW, ox = pt - oy * TW;
            g[u] = (((size_t)b * IMG + (ty0 + oy)) * IMG + (tx0 + ox)) * CCH + (size_t)c4 * 4;
            v[u] = __ldcs(reinterpret_cast<const float4*>(x + g[u]));
            a[u] = s_att[pt];
        }
        #pragma unroll
        for (int u = 0; u < 2; u++) {
            float4 r = v[u]; float s = a[u];
            r.x *= s; r.y *= s; r.z *= s; r.w *= s;
            __stcs(reinterpret_cast<float4*>(out + g[u]), r);
        }
    }
}

extern "C" void kernel_launch(void* const* d_in, const int* in_sizes, int n_in,
                              void* d_out, int out_size)
{
    const float* x = (const float*)d_in[0];
    const float* w = (const float*)d_in[1];
    float* out = (float*)d_out;

    reduce_kernel<<<NPAIR / NW, NT>>>(x);                 // 25088 blocks

    const int TPX = IMG / TW, TPY = IMG / TH;             // 4, 14
    apply_kernel<<<32 * TPX * TPY, NT>>>(x, w, out);      // 1792 blocks
}